// round 15
// baseline (speedup 1.0000x reference)
#include <cuda_runtime.h>
#include <cstddef>

// GraphConvS: out[b,i,f] = sum_j adj[b,i,j] * (concat(sf1,sf2)[b,i,j,:] . W[:,f] + bias[f])
//           = (sum_{j: adj=1} x[b,i,j,:]) . W + deg[b,i] * bias      (adjacency is binary)
//
// One warp per TWO rows (ILP: both rows' DRAM latencies overlap in-flight).
// Per row: ballot+popc compaction of active neighbors into a shared list,
// then a dependence-free gather (4 neighbor-slots x 8 lanes, float4/lane =
// full 128B feature row). Epilogue GEMV vs W transposed in shared.

static constexpr int Bdim    = 64;
static constexpr int Mdim    = 128;
static constexpr int Fhalf   = 32;
static constexpr int FILTERS = 32;
static constexpr int WARPS_PER_CTA = 4;
static constexpr int ROWS_PER_WARP = 2;
static constexpr int ROWS = Bdim * Mdim;                     // 8192
static constexpr int ROWS_PER_CTA = WARPS_PER_CTA * ROWS_PER_WARP; // 8
static constexpr int WT_STRIDE = 68;   // 68 % 32 == 4 -> LDS.128 phase-conflict-free

__global__ void __launch_bounds__(WARPS_PER_CTA * 32, 8)
graphconvs_kernel(const float* __restrict__ sf1,
                  const float* __restrict__ sf2,
                  const float* __restrict__ adj,
                  const float* __restrict__ W,     // [64, 32] row-major (k, f)
                  const float* __restrict__ bias,  // [32]
                  float* __restrict__ out)         // [B*M, 32]
{
    __shared__ float         WTs[FILTERS][WT_STRIDE];          // WT[f][k] = W[k][f]
    __shared__ float         sacc[WARPS_PER_CTA][2][64];
    __shared__ unsigned char jl[WARPS_PER_CTA][2][Mdim];       // compacted neighbor ids

    const int tid  = threadIdx.x;
    const int warp = tid >> 5;
    const int lane = tid & 31;
    const int rowA = blockIdx.x * ROWS_PER_CTA + warp * 2;
    const int rowB = rowA + 1;

    // issue early: bias + both adjacency rows (three independent loads in flight)
    const float bl = __ldg(&bias[lane]);
    const float4 avA = __ldg((const float4*)(adj + (size_t)rowA * Mdim) + lane);
    const float4 avB = __ldg((const float4*)(adj + (size_t)rowB * Mdim) + lane);

    // ---- stage W transposed into shared (float4 loads, scatter stores) ----
    {
        const float4* W4 = (const float4*)W;   // 512 float4's
        #pragma unroll
        for (int q = 0; q < 4; ++q) {
            const int idx = tid + q * 128;     // float4 index
            const float4 w = __ldg(&W4[idx]);
            const int k = idx >> 3;            // (idx*4) / 32
            const int f = (idx & 7) * 4;
            WTs[f + 0][k] = w.x;  WTs[f + 1][k] = w.y;
            WTs[f + 2][k] = w.z;  WTs[f + 3][k] = w.w;
        }
    }

    const unsigned FULL = 0xffffffffu;
    const unsigned lt = (1u << lane) - 1u;

    // row A compaction
    const unsigned a0 = __ballot_sync(FULL, avA.x != 0.0f);
    const unsigned a1 = __ballot_sync(FULL, avA.y != 0.0f);
    const unsigned a2 = __ballot_sync(FULL, avA.z != 0.0f);
    const unsigned a3 = __ballot_sync(FULL, avA.w != 0.0f);
    const int ac0 = __popc(a0);
    const int ac1 = ac0 + __popc(a1);
    const int ac2 = ac1 + __popc(a2);
    const int totalA = ac2 + __popc(a3);
    unsigned char* jlA = jl[warp][0];
    if (avA.x != 0.0f) jlA[      __popc(a0 & lt)] = (unsigned char)(4 * lane + 0);
    if (avA.y != 0.0f) jlA[ac0 + __popc(a1 & lt)] = (unsigned char)(4 * lane + 1);
    if (avA.z != 0.0f) jlA[ac1 + __popc(a2 & lt)] = (unsigned char)(4 * lane + 2);
    if (avA.w != 0.0f) jlA[ac2 + __popc(a3 & lt)] = (unsigned char)(4 * lane + 3);

    // row B compaction
    const unsigned b0 = __ballot_sync(FULL, avB.x != 0.0f);
    const unsigned b1 = __ballot_sync(FULL, avB.y != 0.0f);
    const unsigned b2 = __ballot_sync(FULL, avB.z != 0.0f);
    const unsigned b3 = __ballot_sync(FULL, avB.w != 0.0f);
    const int bc0 = __popc(b0);
    const int bc1 = bc0 + __popc(b1);
    const int bc2 = bc1 + __popc(b2);
    const int totalB = bc2 + __popc(b3);
    unsigned char* jlB = jl[warp][1];
    if (avB.x != 0.0f) jlB[      __popc(b0 & lt)] = (unsigned char)(4 * lane + 0);
    if (avB.y != 0.0f) jlB[bc0 + __popc(b1 & lt)] = (unsigned char)(4 * lane + 1);
    if (avB.z != 0.0f) jlB[bc1 + __popc(b2 & lt)] = (unsigned char)(4 * lane + 2);
    if (avB.w != 0.0f) jlB[bc2 + __popc(b3 & lt)] = (unsigned char)(4 * lane + 3);
    __syncwarp();

    const float degA = (float)totalA;   // adjacency is binary
    const float degB = (float)totalB;

    // ---- fused gather for both rows: slot g takes entries t = g, g+4, ... ----
    const float4* x1A = (const float4*)(sf1 + (size_t)rowA * Mdim * Fhalf);
    const float4* x2A = (const float4*)(sf2 + (size_t)rowA * Mdim * Fhalf);
    const float4* x1B = (const float4*)(sf1 + (size_t)rowB * Mdim * Fhalf);
    const float4* x2B = (const float4*)(sf2 + (size_t)rowB * Mdim * Fhalf);

    const int g  = lane >> 3;   // neighbor slot 0..3
    const int cq = lane & 7;    // channel quad 0..7

    float4 acc1A = make_float4(0.f, 0.f, 0.f, 0.f);
    float4 acc2A = make_float4(0.f, 0.f, 0.f, 0.f);
    float4 acc1B = make_float4(0.f, 0.f, 0.f, 0.f);
    float4 acc2B = make_float4(0.f, 0.f, 0.f, 0.f);

    const int tmax = totalA > totalB ? totalA : totalB;
    #pragma unroll 2
    for (int t = g; t < tmax; t += 4) {
        if (t < totalA) {
            const int idx = (int)jlA[t] * 8 + cq;
            const float4 v1 = __ldg(&x1A[idx]);
            const float4 v2 = __ldg(&x2A[idx]);
            acc1A.x += v1.x; acc1A.y += v1.y; acc1A.z += v1.z; acc1A.w += v1.w;
            acc2A.x += v2.x; acc2A.y += v2.y; acc2A.z += v2.z; acc2A.w += v2.w;
        }
        if (t < totalB) {
            const int idx = (int)jlB[t] * 8 + cq;
            const float4 v1 = __ldg(&x1B[idx]);
            const float4 v2 = __ldg(&x2B[idx]);
            acc1B.x += v1.x; acc1B.y += v1.y; acc1B.z += v1.z; acc1B.w += v1.w;
            acc2B.x += v2.x; acc2B.y += v2.y; acc2B.z += v2.z; acc2B.w += v2.w;
        }
    }

    // ---- merge the 4 neighbor-slot partials (xor 8, 16), both rows ----
    #pragma unroll
    for (int off = 8; off <= 16; off <<= 1) {
        acc1A.x += __shfl_xor_sync(FULL, acc1A.x, off);
        acc1A.y += __shfl_xor_sync(FULL, acc1A.y, off);
        acc1A.z += __shfl_xor_sync(FULL, acc1A.z, off);
        acc1A.w += __shfl_xor_sync(FULL, acc1A.w, off);
        acc2A.x += __shfl_xor_sync(FULL, acc2A.x, off);
        acc2A.y += __shfl_xor_sync(FULL, acc2A.y, off);
        acc2A.z += __shfl_xor_sync(FULL, acc2A.z, off);
        acc2A.w += __shfl_xor_sync(FULL, acc2A.w, off);
        acc1B.x += __shfl_xor_sync(FULL, acc1B.x, off);
        acc1B.y += __shfl_xor_sync(FULL, acc1B.y, off);
        acc1B.z += __shfl_xor_sync(FULL, acc1B.z, off);
        acc1B.w += __shfl_xor_sync(FULL, acc1B.w, off);
        acc2B.x += __shfl_xor_sync(FULL, acc2B.x, off);
        acc2B.y += __shfl_xor_sync(FULL, acc2B.y, off);
        acc2B.z += __shfl_xor_sync(FULL, acc2B.z, off);
        acc2B.w += __shfl_xor_sync(FULL, acc2B.w, off);
    }
    if (lane < 8) {
        ((float4*)&sacc[warp][0][0])[lane]  = acc1A;   // k = lane*4..+3
        ((float4*)&sacc[warp][0][32])[lane] = acc2A;   // k = 32+lane*4..+3
        ((float4*)&sacc[warp][1][0])[lane]  = acc1B;
        ((float4*)&sacc[warp][1][32])[lane] = acc2B;
    }
    __syncthreads();   // orders WTs (and sacc) writes before reads

    // ---- epilogue GEMV for both rows: r[f] = deg*bias[f] + sum_k acc[k]*WT[f][k] ----
    float pA0 = 0.f, pA1 = 0.f, pB0 = 0.f, pB1 = 0.f;
    #pragma unroll
    for (int k4 = 0; k4 < 16; ++k4) {
        const float4 w  = *(const float4*)&WTs[lane][k4 * 4];     // conflict-free
        const float4 sA = *(const float4*)&sacc[warp][0][k4 * 4]; // broadcast
        const float4 sB = *(const float4*)&sacc[warp][1][k4 * 4]; // broadcast
        pA0 = fmaf(sA.x, w.x, pA0); pA1 = fmaf(sA.y, w.y, pA1);
        pA0 = fmaf(sA.z, w.z, pA0); pA1 = fmaf(sA.w, w.w, pA1);
        pB0 = fmaf(sB.x, w.x, pB0); pB1 = fmaf(sB.y, w.y, pB1);
        pB0 = fmaf(sB.z, w.z, pB0); pB1 = fmaf(sB.w, w.w, pB1);
    }
    out[(size_t)rowA * FILTERS + lane] = fmaf(degA, bl, pA0 + pA1);
    out[(size_t)rowB * FILTERS + lane] = fmaf(degB, bl, pB0 + pB1);
}

extern "C" void kernel_launch(void* const* d_in, const int* in_sizes, int n_in,
                              void* d_out, int out_size)
{
    // metadata order: scalar_features_1, scalar_features_2, adjacency, W, b
    const float* sf1  = (const float*)d_in[0];
    const float* sf2  = (const float*)d_in[1];
    const float* adj  = (const float*)d_in[2];
    const float* W    = (const float*)d_in[3];
    const float* bias = (const float*)d_in[4];
    float* out = (float*)d_out;

    graphconvs_kernel<<<ROWS / ROWS_PER_CTA, WARPS_PER_CTA * 32>>>(
        sf1, sf2, adj, W, bias, out);
}